// round 12
// baseline (speedup 1.0000x reference)
#include <cuda_runtime.h>
#include <math.h>

#define D_MODEL   1024
#define SEQ_LEN   32768
#define NBLK_A    592                  // 4 blocks x 148 SMs: exactly one wave
#define NTILES    2048                 // tiles of 16 l (2048*16 = 32768)

#define TWO_PI    6.283185307179586f
#define INV_2PI   0.15915494309189535f
#define MAGIC     12582912.0f          // 1.5 * 2^23
#define C1_2PI    6.28318548202514648f // fl32(2*pi)
#define INV1023   (1.0f / 1023.0f)

typedef unsigned long long ull;

// Scratch (device globals; no allocation in kernel_launch)
// TRANSPOSED: g_part[col][slice]; col i = m*32+k packs d=(32k+2m, 32k+2m+1),
// sign-twisted by sigma_m. A stores scattered (hidden), B loads coalesced.
__device__ ull g_part[512 * NBLK_A];
__device__ __align__(16) float g_signal[D_MODEL];

// ---------------- packed f32x2 helpers --------------------------------------
__device__ __forceinline__ ull fma2(ull a, ull b, ull c) {
    ull d; asm("fma.rn.f32x2 %0,%1,%2,%3;" : "=l"(d) : "l"(a), "l"(b), "l"(c)); return d;
}
__device__ __forceinline__ ull add2(ull a, ull b) {
    ull d; asm("add.rn.f32x2 %0,%1,%2;" : "=l"(d) : "l"(a), "l"(b)); return d;
}
__device__ __forceinline__ ull pk2(float lo, float hi) {
    ull d; asm("mov.b64 %0,{%1,%2};" : "=l"(d) : "f"(lo), "f"(hi)); return d;
}
__device__ __forceinline__ float2 unpk(ull v) {
    float2 r; asm("mov.b64 {%0,%1},%2;" : "=f"(r.x), "=f"(r.y) : "l"(v)); return r;
}

// ---------------------------------------------------------------------------
// Kernel A: persistent single-wave sin partial sums.
// Block loops over 16-l tiles (static stride schedule); per tile each warp
// runs TWO interleaved l-chains of the packed-pair Chebyshev recurrence over
// d. Lane k owns d=32k..32k+31 as 16 packed pairs; acc persists across tiles.
// ---------------------------------------------------------------------------
__global__ void __launch_bounds__(256, 4)
sinsum_kernel(const float* __restrict__ inputs) {
    __shared__ float4 co[2][16];       // (a, a*log1p(l), 2cos(dl), 2cos(2dl))
    __shared__ ull    sred[4 * 512];   // 16KB two-phase epilogue buffer

    const int tid = threadIdx.x;
    const int w   = tid >> 5;
    const int k   = tid & 31;
    const float tk = (float)(32 * k) * INV1023;

    ull acc[16];
#pragma unroll
    for (int m = 0; m < 16; ++m) acc[m] = 0ull;

    int buf = 0;
    for (int t = blockIdx.x; t < NTILES; t += NBLK_A) {
        if (tid < 16) {
            const int l = t * 16 + tid;
            float x  = inputs[l];
            float a  = TWO_PI * x;
            float p  = log1pf((float)l);
            float dl = a * INV1023;
            float d2 = dl * dl;
            float u2 = 4.0f * d2;                     // (2*dl)^2
            float c  = fmaf(d2, fmaf(d2, fmaf(d2, -(1.0f/360.0f), (1.0f/12.0f)), -1.0f), 2.0f);
            float c2 = fmaf(u2, fmaf(u2, fmaf(u2, -(1.0f/360.0f), (1.0f/12.0f)), -1.0f), 2.0f);
            co[buf][tid] = make_float4(a, a * p, c, c2);
        }
        __syncthreads();

        float4 CA = co[buf][2 * w];
        float4 CB = co[buf][2 * w + 1];
        buf ^= 1;

        // --- seeds for chain A and chain B (independent) ---
        float phiA = fmaf(CA.x, tk, CA.y);
        float phiB = fmaf(CB.x, tk, CB.y);
        float yA   = fmaf(phiA, INV_2PI, MAGIC);
        float yB   = fmaf(phiB, INV_2PI, MAGIC);
        float rA   = fmaf(yA - MAGIC, -C1_2PI, phiA);
        float rB   = fmaf(yB - MAGIC, -C1_2PI, phiB);
        float dlA  = CA.x * INV1023;
        float dlB  = CB.x * INV1023;
        float sA0  = __sinf(rA);
        float sB0  = __sinf(rB);
        float sA1  = __sinf(rA + dlA);
        float sB1  = __sinf(rB + dlB);
        float sA2  = fmaf(CA.z, sA1, -sA0);
        float sB2  = fmaf(CB.z, sB1, -sB0);
        float sA3  = fmaf(CA.z, sA2, -sA1);
        float sB3  = fmaf(CB.z, sB2, -sB1);

        ull a0 = pk2(sA0, sA1), a1 = pk2(sA2, sA3);
        ull b0 = pk2(sB0, sB1), b1 = pk2(sB2, sB3);
        ull cAp = pk2(CA.w, CA.w), cAn = pk2(-CA.w, -CA.w);
        ull cBp = pk2(CB.w, CB.w), cBn = pk2(-CB.w, -CB.w);

        acc[0] = add2(acc[0], add2(a0, b0));
        acc[1] = add2(acc[1], add2(a1, b1));

#pragma unroll
        for (int m = 2; m < 16; ++m) {
            // sign-twisted: a_m = fma2(m odd ? +c2 : -c2, a_{m-1}, a_{m-2})
            ull an = fma2((m & 1) ? cAp : cAn, a1, a0);
            ull bn = fma2((m & 1) ? cBp : cBn, b1, b0);
            acc[m] = add2(acc[m], add2(an, bn));
            a0 = a1; a1 = an;
            b0 = b1; b1 = bn;
        }
    }

    // Epilogue phase 1: warps 4..7 stage.
    __syncthreads();
    if (w >= 4) {
#pragma unroll
        for (int m = 0; m < 16; ++m)
            sred[(w - 4) * 512 + m * 32 + k] = acc[m];
    }
    __syncthreads();
    // Phase 2: warps 0..3 add in place.
    if (w < 4) {
#pragma unroll
        for (int m = 0; m < 16; ++m) {
            const int i = w * 512 + m * 32 + k;
            sred[i] = add2(sred[i], acc[m]);
        }
    }
    __syncthreads();

    // Gather 4 segments, transposed (scattered) store to g_part[col][slice].
#pragma unroll
    for (int rep = 0; rep < 2; ++rep) {
        const int i = tid + rep * 256;
        ull s = add2(add2(sred[i], sred[512 + i]),
                     add2(sred[1024 + i], sred[1536 + i]));
        g_part[i * NBLK_A + blockIdx.x] = s;
    }
}

// ---------------------------------------------------------------------------
// Kernel B: reduce each packed column over 592 slices (coalesced), undo
// sigma, emit signal. 64 blocks x 256 threads; warp per column.
// ---------------------------------------------------------------------------
__global__ void __launch_bounds__(256)
reduce_kernel() {
    const int tid  = threadIdx.x;
    const int lane = tid & 31;
    const int col  = blockIdx.x * 8 + (tid >> 5);     // 0..511

    const ull* src = &g_part[col * NBLK_A];
    ull s = 0ull;
    for (int j = lane; j < NBLK_A; j += 32)
        s = add2(s, src[j]);
#pragma unroll
    for (int off = 16; off > 0; off >>= 1)
        s = add2(s, __shfl_down_sync(0xffffffffu, s, off));

    if (lane == 0) {
        const int m  = col >> 5;
        const int kk = col & 31;
        const float sg = ((m >> 1) & 1) ? -1.0f : 1.0f;   // undo sigma_m
        float2 v = unpk(s);
        const int d0 = 32 * kk + 2 * m;
        g_signal[d0]     = sg * v.x;
        g_signal[d0 + 1] = sg * v.y;
    }
}

// ---------------------------------------------------------------------------
// Kernel C: GEMV out = signal @ W^T + b. 256 blocks x 128 thr, warp per row.
// ---------------------------------------------------------------------------
__global__ void __launch_bounds__(128)
gemv_kernel(const float* __restrict__ W, const float* __restrict__ bias,
            float* __restrict__ out) {
    __shared__ __align__(16) float ssig[D_MODEL];

    const int tid = threadIdx.x;
#pragma unroll
    for (int i = tid; i < D_MODEL / 4; i += 128)
        ((float4*)ssig)[i] = ((const float4*)g_signal)[i];
    __syncthreads();

    const int warp = tid >> 5;
    const int lane = tid & 31;
    const int row  = blockIdx.x * 4 + warp;

    const float4* w4 = (const float4*)(W + row * D_MODEL);
    float acc = 0.0f;
#pragma unroll
    for (int kk = lane; kk < D_MODEL / 4; kk += 32) {
        float4 wv = w4[kk];
        float4 sv = ((const float4*)ssig)[kk];
        acc = fmaf(wv.x, sv.x, acc);
        acc = fmaf(wv.y, sv.y, acc);
        acc = fmaf(wv.z, sv.z, acc);
        acc = fmaf(wv.w, sv.w, acc);
    }
#pragma unroll
    for (int off = 16; off > 0; off >>= 1)
        acc += __shfl_down_sync(0xffffffffu, acc, off);

    if (lane == 0) out[row] = acc + bias[row];
}

// ---------------------------------------------------------------------------
extern "C" void kernel_launch(void* const* d_in, const int* in_sizes, int n_in,
                              void* d_out, int out_size) {
    const float* inputs = (const float*)d_in[0];   // [32768]
    const float* W      = (const float*)d_in[1];   // [1024,1024]
    const float* b      = (const float*)d_in[2];   // [1024]
    float*       out    = (float*)d_out;           // [1024]

    sinsum_kernel<<<NBLK_A, 256>>>(inputs);
    reduce_kernel<<<64, 256>>>();
    gemv_kernel<<<D_MODEL / 4, 128>>>(W, b, out);
    (void)in_sizes; (void)n_in; (void)out_size;
}

// round 13
// speedup vs baseline: 1.4341x; 1.4341x over previous
#include <cuda_runtime.h>
#include <math.h>

#define D_MODEL   1024
#define SEQ_LEN   32768
#define NBLK_A    512                   // phase-A blocks
#define LPB       64                    // l's per block
#define LPW       8                     // l's per warp (8 warps/block)

#define TWO_PI    6.283185307179586f
#define INV_2PI   0.15915494309189535f
#define MAGIC     12582912.0f           // 1.5 * 2^23
#define C1_2PI    6.28318548202514648f  // fl32(2*pi)
#define INV1023   (1.0f / 1023.0f)

typedef unsigned long long ull;

// Scratch (device globals; no allocation in kernel_launch)
// g_part[slice][col]; col i = m*32+k packs d=(32k+2m, 32k+2m+1),
// sign-twisted by sigma_m. A stores coalesced; B reads lane->col coalesced.
__device__ ull g_part[NBLK_A * 512];               // 2 MB
__device__ __align__(16) float g_signal[D_MODEL];

// ---------------- packed f32x2 helpers --------------------------------------
__device__ __forceinline__ ull fma2(ull a, ull b, ull c) {
    ull d; asm("fma.rn.f32x2 %0,%1,%2,%3;" : "=l"(d) : "l"(a), "l"(b), "l"(c)); return d;
}
__device__ __forceinline__ ull add2(ull a, ull b) {
    ull d; asm("add.rn.f32x2 %0,%1,%2;" : "=l"(d) : "l"(a), "l"(b)); return d;
}
__device__ __forceinline__ ull pk2(float lo, float hi) {
    ull d; asm("mov.b64 %0,{%1,%2};" : "=l"(d) : "f"(lo), "f"(hi)); return d;
}
__device__ __forceinline__ float2 unpk(ull v) {
    float2 r; asm("mov.b64 {%0,%1},%2;" : "=f"(r.x), "=f"(r.y) : "l"(v)); return r;
}

// ---------------------------------------------------------------------------
// Kernel A: packed-pair Chebyshev recurrence over d, TWO interleaved l-chains
// per iteration for ILP. Lane k owns d=32k..32k+31 as 16 packed pairs.
// (Exact R8 structure: coalesced epilogue store.)
// ---------------------------------------------------------------------------
__global__ void __launch_bounds__(256, 4)
sinsum_kernel(const float* __restrict__ inputs) {
    __shared__ float4 co[LPB];        // (a, a*log1p(l), 2cos(dl), 2cos(2dl))
    __shared__ ull    sred[8 * 512];  // 32KB packed cross-warp buffer

    const int tid = threadIdx.x;
    const int w   = tid >> 5;
    const int k   = tid & 31;

    if (tid < LPB) {
        const int l = blockIdx.x * LPB + tid;
        float x  = inputs[l];
        float a  = TWO_PI * x;
        float p  = log1pf((float)l);
        float dl = a * INV1023;
        float d2 = dl * dl;
        float u2 = 4.0f * d2;                         // (2*dl)^2
        float c  = fmaf(d2, fmaf(d2, fmaf(d2, -(1.0f/360.0f), (1.0f/12.0f)), -1.0f), 2.0f);
        float c2 = fmaf(u2, fmaf(u2, fmaf(u2, -(1.0f/360.0f), (1.0f/12.0f)), -1.0f), 2.0f);
        co[tid]  = make_float4(a, a * p, c, c2);
    }
    __syncthreads();

    const float tk = (float)(32 * k) * INV1023;

    ull acc[16];
#pragma unroll
    for (int m = 0; m < 16; ++m) acc[m] = 0ull;

#pragma unroll 1
    for (int jp = 0; jp < LPW / 2; ++jp) {
        float4 CA = co[w * LPW + 2 * jp];
        float4 CB = co[w * LPW + 2 * jp + 1];

        // --- seeds for chain A and chain B (independent) ---
        float phiA = fmaf(CA.x, tk, CA.y);
        float phiB = fmaf(CB.x, tk, CB.y);
        float yA   = fmaf(phiA, INV_2PI, MAGIC);
        float yB   = fmaf(phiB, INV_2PI, MAGIC);
        float rA   = fmaf(yA - MAGIC, -C1_2PI, phiA);
        float rB   = fmaf(yB - MAGIC, -C1_2PI, phiB);
        float dlA  = CA.x * INV1023;
        float dlB  = CB.x * INV1023;
        float sA0  = __sinf(rA);
        float sB0  = __sinf(rB);
        float sA1  = __sinf(rA + dlA);
        float sB1  = __sinf(rB + dlB);
        float sA2  = fmaf(CA.z, sA1, -sA0);
        float sB2  = fmaf(CB.z, sB1, -sB0);
        float sA3  = fmaf(CA.z, sA2, -sA1);
        float sB3  = fmaf(CB.z, sB2, -sB1);

        ull a0 = pk2(sA0, sA1), a1 = pk2(sA2, sA3);
        ull b0 = pk2(sB0, sB1), b1 = pk2(sB2, sB3);
        ull cAp = pk2(CA.w, CA.w), cAn = pk2(-CA.w, -CA.w);
        ull cBp = pk2(CB.w, CB.w), cBn = pk2(-CB.w, -CB.w);

        acc[0] = add2(acc[0], add2(a0, b0));
        acc[1] = add2(acc[1], add2(a1, b1));

#pragma unroll
        for (int m = 2; m < 16; ++m) {
            // sign-twisted: a_m = fma2(m odd ? +c2 : -c2, a_{m-1}, a_{m-2})
            ull an = fma2((m & 1) ? cAp : cAn, a1, a0);
            ull bn = fma2((m & 1) ? cBp : cBn, b1, b0);
            acc[m] = add2(acc[m], add2(an, bn));
            a0 = a1; a1 = an;
            b0 = b1; b1 = bn;
        }
    }

    // Epilogue: packed cross-warp reduce, coalesced store.
#pragma unroll
    for (int m = 0; m < 16; ++m)
        sred[w * 512 + m * 32 + k] = acc[m];
    __syncthreads();

#pragma unroll
    for (int rep = 0; rep < 2; ++rep) {
        const int i = tid + rep * 256;
        ull s = sred[i];
#pragma unroll
        for (int ww = 1; ww < 8; ++ww)
            s = add2(s, sred[ww * 512 + i]);
        g_part[blockIdx.x * 512 + i] = s;             // STG.64 coalesced
    }
}

// ---------------------------------------------------------------------------
// Kernel B: reduce 512 slices per packed column. 16 blocks x 512 threads.
// Lane -> column (32 consecutive u64 per warp load = 256B coalesced);
// warp w covers slices w, w+16, w+32, ... (32 each). Smem tree over 16
// warps, sigma-unmap, write signal. Block b owns columns 32b..32b+31
// (all share m = b, so sigma is uniform per block).
// ---------------------------------------------------------------------------
__global__ void __launch_bounds__(512)
reduce_kernel() {
    __shared__ ull sb[16][33];
    const int tid  = threadIdx.x;
    const int w    = tid >> 5;                        // 0..15
    const int lane = tid & 31;
    const int col  = blockIdx.x * 32 + lane;          // m = blockIdx.x, k = lane

    ull s = 0ull;
#pragma unroll 8
    for (int j = 0; j < 32; ++j)
        s = add2(s, g_part[(w + 16 * j) * 512 + col]);
    sb[w][lane] = s;
    __syncthreads();

    if (tid < 32) {
        ull tot = sb[0][tid];
#pragma unroll
        for (int ww = 1; ww < 16; ++ww)
            tot = add2(tot, sb[ww][tid]);
        const int m = blockIdx.x;
        const float sg = ((m >> 1) & 1) ? -1.0f : 1.0f;   // undo sigma_m
        float2 v = unpk(tot);
        const int d0 = 32 * tid + 2 * m;
        g_signal[d0]     = sg * v.x;
        g_signal[d0 + 1] = sg * v.y;
    }
}

// ---------------------------------------------------------------------------
// Kernel C: GEMV out = signal @ W^T + b. 256 blocks x 128 thr, warp per row.
// ---------------------------------------------------------------------------
__global__ void __launch_bounds__(128)
gemv_kernel(const float* __restrict__ W, const float* __restrict__ bias,
            float* __restrict__ out) {
    __shared__ __align__(16) float ssig[D_MODEL];

    const int tid = threadIdx.x;
#pragma unroll
    for (int i = tid; i < D_MODEL / 4; i += 128)
        ((float4*)ssig)[i] = ((const float4*)g_signal)[i];
    __syncthreads();

    const int warp = tid >> 5;
    const int lane = tid & 31;
    const int row  = blockIdx.x * 4 + warp;

    const float4* w4 = (const float4*)(W + row * D_MODEL);
    float acc = 0.0f;
#pragma unroll
    for (int kk = lane; kk < D_MODEL / 4; kk += 32) {
        float4 wv = w4[kk];
        float4 sv = ((const float4*)ssig)[kk];
        acc = fmaf(wv.x, sv.x, acc);
        acc = fmaf(wv.y, sv.y, acc);
        acc = fmaf(wv.z, sv.z, acc);
        acc = fmaf(wv.w, sv.w, acc);
    }
#pragma unroll
    for (int off = 16; off > 0; off >>= 1)
        acc += __shfl_down_sync(0xffffffffu, acc, off);

    if (lane == 0) out[row] = acc + bias[row];
}

// ---------------------------------------------------------------------------
extern "C" void kernel_launch(void* const* d_in, const int* in_sizes, int n_in,
                              void* d_out, int out_size) {
    const float* inputs = (const float*)d_in[0];   // [32768]
    const float* W      = (const float*)d_in[1];   // [1024,1024]
    const float* b      = (const float*)d_in[2];   // [1024]
    float*       out    = (float*)d_out;           // [1024]

    sinsum_kernel<<<NBLK_A, 256>>>(inputs);
    reduce_kernel<<<16, 512>>>();
    gemv_kernel<<<D_MODEL / 4, 128>>>(W, b, out);
    (void)in_sizes; (void)n_in; (void)out_size;
}